// round 10
// baseline (speedup 1.0000x reference)
#include <cuda_runtime.h>
#include <cuda_bf16.h>
#include <mma.h>
#include <math.h>

using namespace nvcuda;

#define NN 33
#define TT 1024
#define EE 97
#define H1 8
#define HC 512
#define C2 512
#define HID1 128
#define Z1 512
#define NC2 16896
#define HID2 64
#define Z2 256
#define WREG 96
#define WSM  32   // WREG + WSM == HID1

typedef unsigned long long ull;

__device__ float d_ep1[EE * HC];
__device__ float d_ep2[EE * C2];
__device__ int   d_csr_start[NN + 1];
__device__ int   d_csr_eid[EE];
__device__ int   d_src[EE];
__device__ int   d_dst[EE];
__device__ __align__(16) __nv_bfloat16 d_h1hi[TT * NN * HC];
__device__ __align__(16) __nv_bfloat16 d_h1lo[TT * NN * HC];
__device__ __align__(16) __nv_bfloat16 d_g2bhi[512 * 1024];
__device__ __align__(16) __nv_bfloat16 d_g2blo[512 * 1024];
__device__ __align__(16) __nv_bfloat16 d_seqh[NN * TT * C2];
__device__ __align__(16) __nv_bfloat16 d_seql[NN * TT * C2];
__device__ __align__(16) __nv_bfloat16 d_wihh[(long)Z1 * NC2];
__device__ __align__(16) __nv_bfloat16 d_wihl[(long)Z1 * NC2];
__device__ float d_hl[TT * NN * C2];
__device__ float d_hr[TT * NN * C2];
__device__ float d_xpre1[TT * Z1];
__device__ float d_hs1[TT * HID1];
__device__ float d_xpre2[TT * Z2];
__device__ float d_lb1[Z1];
__device__ float d_lb2[Z2];

__device__ __forceinline__ float sigm(float x) { return 1.0f / (1.0f + expf(-x)); }

__device__ __forceinline__ ull ffma2(ull a, ull b, ull c) {
    ull d;
    asm("fma.rn.f32x2 %0, %1, %2, %3;" : "=l"(d) : "l"(a), "l"(b), "l"(c));
    return d;
}
__device__ __forceinline__ ull pk2(float lo, float hi) {
    ull r;
    asm("mov.b64 %0, {%1, %2};" : "=l"(r) : "f"(lo), "f"(hi));
    return r;
}
__device__ __forceinline__ float2 upk2(ull v) {
    float2 f;
    asm("mov.b64 {%0, %1}, %2;" : "=f"(f.x), "=f"(f.y) : "l"(v));
    return f;
}
__device__ __forceinline__ void cpa16(void* s, const void* g) {
    unsigned sa = (unsigned)__cvta_generic_to_shared(s);
    asm volatile("cp.async.cg.shared.global [%0], [%1], 16;" :: "r"(sa), "l"(g));
}
__device__ __forceinline__ void cpa_commit() { asm volatile("cp.async.commit_group;"); }

// ---------- K0: setup ----------
__global__ __launch_bounds__(512) void k_setup(const int* __restrict__ ei, const float* __restrict__ ea,
                        const float* __restrict__ g1_we, const float* __restrict__ g2_we,
                        const float* __restrict__ b1i, const float* __restrict__ b1h,
                        const float* __restrict__ b2i, const float* __restrict__ b2h) {
    __shared__ int cnt[NN + 1];
    __shared__ int pos[NN];
    int tid = threadIdx.x;
    if (tid == 0) {
        for (int n = 0; n <= NN; n++) cnt[n] = 0;
        for (int e = 0; e < EE; e++) {
            d_src[e] = ei[e];
            d_dst[e] = ei[EE + e];
            cnt[ei[EE + e] + 1]++;
        }
        for (int n = 0; n < NN; n++) cnt[n + 1] += cnt[n];
        for (int n = 0; n <= NN; n++) d_csr_start[n] = cnt[n];
        for (int n = 0; n < NN; n++) pos[n] = cnt[n];
        for (int e = 0; e < EE; e++) d_csr_eid[pos[ei[EE + e]]++] = e;
    }
    for (int e = 0; e < EE; e++) {
        float a0 = ea[e * 3], a1 = ea[e * 3 + 1], a2 = ea[e * 3 + 2];
        d_ep1[e * HC + tid] = a0 * g1_we[tid] + a1 * g1_we[HC + tid] + a2 * g1_we[2 * HC + tid];
        d_ep2[e * C2 + tid] = a0 * g2_we[tid] + a1 * g2_we[C2 + tid] + a2 * g2_we[2 * C2 + tid];
    }
    d_lb1[tid] = b1i[tid] + b1h[tid];
    if (tid < Z2) d_lb2[tid] = b2i[tid] + b2h[tid];
}

// ---------- K0b: split gemm1 B into bf16 hi/lo ----------
__global__ __launch_bounds__(256) void k_split_w1(const float* __restrict__ wl,
                                                  const float* __restrict__ wr) {
    int k = blockIdx.x;
    for (int n = threadIdx.x; n < 1024; n += 256) {
        float v = (n < 512) ? wl[k * 512 + n] : wr[k * 512 + (n - 512)];
        __nv_bfloat16 hi = __float2bfloat16(v);
        d_g2bhi[k * 1024 + n] = hi;
        d_g2blo[k * 1024 + n] = __float2bfloat16(v - __bfloat162float(hi));
    }
}

// ---------- K0c: split l1_wih into bf16 hi/lo ----------
__global__ __launch_bounds__(256) void k_split_w2(const float* __restrict__ w) {
    int n = blockIdx.x;
    for (int k = threadIdx.x; k < NC2; k += 256) {
        float v = w[(long)n * NC2 + k];
        __nv_bfloat16 hi = __float2bfloat16(v);
        d_wihh[(long)n * NC2 + k] = hi;
        d_wihl[(long)n * NC2 + k] = __float2bfloat16(v - __bfloat162float(hi));
    }
}

// ---------- K1: GAT1 (epilogue writes bf16 split of h1) ----------
__global__ __launch_bounds__(512) void k_gat1(const float* __restrict__ x,
                                              const float* __restrict__ wl,
                                              const float* __restrict__ wr,
                                              const float* __restrict__ att,
                                              const float* __restrict__ bias) {
    int t = blockIdx.x;
    int tid = threadIdx.x;
    extern __shared__ float sm[];
    float* xl    = sm;            // 16896
    float* part  = xl + 16896;    // 97*16
    float* logit = part + 1552;   // 97*8
    float* alpha = logit + 776;   // 97*8
    float* sx    = alpha + 776;   // 68
    int* cstart = (int*)(sx + 68);
    int* ceid   = cstart + NN + 1;
    int* csrc   = ceid + EE;
    int* cdst   = csrc + EE;

    if (tid < 2 * NN) sx[tid] = x[t * (2 * NN) + tid];
    if (tid < NN + 1) cstart[tid] = d_csr_start[tid];
    if (tid < EE) { ceid[tid] = d_csr_eid[tid]; csrc[tid] = d_src[tid]; cdst[tid] = d_dst[tid]; }
    float wl0 = wl[tid], wl1 = wl[HC + tid];
    float wr0 = wr[tid], wr1 = wr[HC + tid];
    float attc = att[tid];
    __syncthreads();

    for (int n = 0; n < NN; n++)
        xl[n * HC + tid] = fmaf(sx[2 * n], wl0, sx[2 * n + 1] * wl1);
    __syncthreads();

    int lane = tid & 31, warp = tid >> 5;
#pragma unroll 4
    for (int e = 0; e < EE; e++) {
        int s = csrc[e], d = cdst[e];
        float xr = fmaf(sx[2 * d], wr0, sx[2 * d + 1] * wr1);
        float v = xl[s * HC + tid] + xr + d_ep1[e * HC + tid];
        v = fmaxf(v, 0.2f * v);
        v *= attc;
        v += __shfl_xor_sync(0xffffffffu, v, 16);
        v += __shfl_xor_sync(0xffffffffu, v, 8);
        v += __shfl_xor_sync(0xffffffffu, v, 4);
        v += __shfl_xor_sync(0xffffffffu, v, 2);
        v += __shfl_xor_sync(0xffffffffu, v, 1);
        if (lane == 0) part[e * 16 + warp] = v;
    }
    __syncthreads();
    for (int idx = tid; idx < EE * H1; idx += 512) {
        int e = idx >> 3, h = idx & 7;
        logit[idx] = part[e * 16 + 2 * h] + part[e * 16 + 2 * h + 1];
    }
    __syncthreads();
    for (int idx = tid; idx < NN * H1; idx += 512) {
        int n = idx >> 3, h = idx & 7;
        int s0 = cstart[n], s1 = cstart[n + 1];
        float m = -INFINITY;
        for (int p = s0; p < s1; p++) m = fmaxf(m, logit[ceid[p] * 8 + h]);
        float den = 0.0f;
        for (int p = s0; p < s1; p++) {
            float ex = expf(logit[ceid[p] * 8 + h] - m);
            den += ex;
            alpha[ceid[p] * 8 + h] = ex;
        }
        float inv = 1.0f / (den + 1e-16f);
        for (int p = s0; p < s1; p++) alpha[ceid[p] * 8 + h] *= inv;
    }
    __syncthreads();
    int h = tid >> 6;
    float b = bias[tid];
    for (int n = 0; n < NN; n++) {
        int s0 = cstart[n], s1 = cstart[n + 1];
        float acc = 0.0f;
        for (int p = s0; p < s1; p++) {
            int e = ceid[p];
            acc = fmaf(alpha[e * 8 + h], xl[csrc[e] * HC + tid], acc);
        }
        float o = acc + b;
        o = o > 0.0f ? o : expm1f(o);
        long idx = (long)(t * NN + n) * HC + tid;
        __nv_bfloat16 hi = __float2bfloat16(o);
        d_h1hi[idx] = hi;
        d_h1lo[idx] = __float2bfloat16(o - __bfloat162float(hi));
    }
}

// ---------- K2: GEMM1 wmma — cp.async double-buffered, 128x64, Kc=64 ----------
// per-buffer element layout: Ah 128*72 | Al 128*72 | Bh 64*72 | Bl 64*72 = 27648 elems
#define G1BUF 27648
__global__ __launch_bounds__(256) void k_gemm1() {
    extern __shared__ __align__(16) __nv_bfloat16 smb[];
    int nt = blockIdx.x, mb = blockIdx.y;
    int tid = threadIdx.x, warp = tid >> 5;
    int wm = warp >> 1, wn = warp & 1;

    wmma::fragment<wmma::accumulator, 16, 16, 16, float> acc[2][2];
#pragma unroll
    for (int i = 0; i < 2; i++)
#pragma unroll
        for (int j = 0; j < 2; j++) wmma::fill_fragment(acc[i][j], 0.0f);

    const __nv_bfloat16* Agh = d_h1hi + (long)(mb * 128) * 512;
    const __nv_bfloat16* Agl = d_h1lo + (long)(mb * 128) * 512;
    int arow = tid >> 1;            // for A: 2 threads per row? no — use idx pattern below

    auto load_chunk = [&](int k0, int b) {
        __nv_bfloat16* Ah = smb + b * G1BUF;
        __nv_bfloat16* Al = Ah + 128 * 72;
        __nv_bfloat16* Bh = Al + 128 * 72;
        __nv_bfloat16* Bl = Bh + 64 * 72;
#pragma unroll
        for (int i = 0; i < 4; i++) {
            int idx = tid + i * 256;
            int row = idx >> 3, c8 = (idx & 7) * 8;
            cpa16(&Ah[row * 72 + c8], &Agh[(long)row * 512 + k0 + c8]);
            cpa16(&Al[row * 72 + c8], &Agl[(long)row * 512 + k0 + c8]);
        }
#pragma unroll
        for (int i = 0; i < 2; i++) {
            int idx = tid + i * 256;
            int kr = idx >> 3, c8 = (idx & 7) * 8;
            cpa16(&Bh[kr * 72 + c8], &d_g2bhi[(k0 + kr) * 1024 + nt * 64 + c8]);
            cpa16(&Bl[kr * 72 + c8], &d_g2blo[(k0 + kr) * 1024 + nt * 64 + c8]);
        }
        cpa_commit();
    };

    load_chunk(0, 0);
    for (int ch = 0; ch < 8; ch++) {
        int p = ch & 1;
        if (ch < 7) load_chunk((ch + 1) * 64, p ^ 1);
        if (ch < 7) asm volatile("cp.async.wait_group 1;");
        else        asm volatile("cp.async.wait_group 0;");
        __syncthreads();
        __nv_bfloat16* Ah = smb + p * G1BUF;
        __nv_bfloat16* Al = Ah + 128 * 72;
        __nv_bfloat16* Bh = Al + 128 * 72;
        __nv_bfloat16* Bl = Bh + 64 * 72;
#pragma unroll
        for (int k16 = 0; k16 < 4; k16++) {
            wmma::fragment<wmma::matrix_a, 16, 16, 16, __nv_bfloat16, wmma::row_major> ah[2], al[2];
#pragma unroll
            for (int i = 0; i < 2; i++) {
                wmma::load_matrix_sync(ah[i], Ah + (wm * 32 + i * 16) * 72 + k16 * 16, 72);
                wmma::load_matrix_sync(al[i], Al + (wm * 32 + i * 16) * 72 + k16 * 16, 72);
            }
            wmma::fragment<wmma::matrix_b, 16, 16, 16, __nv_bfloat16, wmma::row_major> bh[2], bl[2];
#pragma unroll
            for (int j = 0; j < 2; j++) {
                wmma::load_matrix_sync(bh[j], Bh + (k16 * 16) * 72 + wn * 32 + j * 16, 72);
                wmma::load_matrix_sync(bl[j], Bl + (k16 * 16) * 72 + wn * 32 + j * 16, 72);
            }
#pragma unroll
            for (int i = 0; i < 2; i++)
#pragma unroll
                for (int j = 0; j < 2; j++) {
                    wmma::mma_sync(acc[i][j], ah[i], bh[j], acc[i][j]);
                    wmma::mma_sync(acc[i][j], ah[i], bl[j], acc[i][j]);
                    wmma::mma_sync(acc[i][j], al[i], bh[j], acc[i][j]);
                }
        }
        __syncthreads();
    }
    float* C = (nt < 8) ? d_hl : d_hr;
    int c0 = (nt & 7) * 64;
#pragma unroll
    for (int i = 0; i < 2; i++)
#pragma unroll
        for (int j = 0; j < 2; j++)
            wmma::store_matrix_sync(C + (long)(mb * 128 + wm * 32 + i * 16) * 512 + c0 + wn * 32 + j * 16,
                                    acc[i][j], 512, wmma::mem_row_major);
}

// ---------- K3: GAT2 (epilogue writes bf16 split of seq) ----------
__global__ __launch_bounds__(512) void k_gat2(const float* __restrict__ att2,
                                              const float* __restrict__ bias2) {
    int t = blockIdx.x;
    int tid = threadIdx.x;
    extern __shared__ float sm[];
    float* hl    = sm;           // 16896
    float* part  = hl + 16896;   // 1552
    float* logit = part + 1552;  // 104
    float* alpha = logit + 104;  // 104
    int* cstart = (int*)(alpha + 104);
    int* ceid   = cstart + NN + 1;
    int* csrc   = ceid + EE;
    int* cdst   = csrc + EE;

    const float4* srcl = (const float4*)(d_hl + (long)t * NC2);
    for (int i = tid; i < NC2 / 4; i += 512)
        ((float4*)hl)[i] = srcl[i];
    if (tid < NN + 1) cstart[tid] = d_csr_start[tid];
    if (tid < EE) { ceid[tid] = d_csr_eid[tid]; csrc[tid] = d_src[tid]; cdst[tid] = d_dst[tid]; }
    float attc = att2[tid];
    float b = bias2[tid];
    const float* hrg = d_hr + (long)t * NC2;
    __syncthreads();

    int lane = tid & 31, warp = tid >> 5;
#pragma unroll 4
    for (int e = 0; e < EE; e++) {
        int s = csrc[e], d = cdst[e];
        float v = hl[s * C2 + tid] + __ldg(hrg + d * C2 + tid) + __ldg(&d_ep2[e * C2 + tid]);
        v = fmaxf(v, 0.2f * v);
        v *= attc;
        v += __shfl_xor_sync(0xffffffffu, v, 16);
        v += __shfl_xor_sync(0xffffffffu, v, 8);
        v += __shfl_xor_sync(0xffffffffu, v, 4);
        v += __shfl_xor_sync(0xffffffffu, v, 2);
        v += __shfl_xor_sync(0xffffffffu, v, 1);
        if (lane == 0) part[e * 16 + warp] = v;
    }
    __syncthreads();
    if (tid < EE) {
        float s = 0.0f;
        for (int w = 0; w < 16; w++) s += part[tid * 16 + w];
        logit[tid] = s;
    }
    __syncthreads();
    if (tid < NN) {
        int s0 = cstart[tid], s1 = cstart[tid + 1];
        float m = -INFINITY;
        for (int p = s0; p < s1; p++) m = fmaxf(m, logit[ceid[p]]);
        float den = 0.0f;
        for (int p = s0; p < s1; p++) {
            float ex = expf(logit[ceid[p]] - m);
            den += ex;
            alpha[ceid[p]] = ex;
        }
        float inv = 1.0f / (den + 1e-16f);
        for (int p = s0; p < s1; p++) alpha[ceid[p]] *= inv;
    }
    __syncthreads();
    for (int n = 0; n < NN; n++) {
        int s0 = cstart[n], s1 = cstart[n + 1];
        float acc = 0.0f;
        for (int p = s0; p < s1; p++) {
            int e = ceid[p];
            acc = fmaf(alpha[e], hl[csrc[e] * C2 + tid], acc);
        }
        float o = acc + b;
        o = o > 0.0f ? o : expm1f(o);
        long idx = ((long)n * TT + t) * C2 + tid;
        __nv_bfloat16 hi = __float2bfloat16(o);
        d_seqh[idx] = hi;
        d_seql[idx] = __float2bfloat16(o - __bfloat162float(hi));
    }
}

// ---------- K4a: init xpre1 with biases ----------
__global__ __launch_bounds__(512) void k_xpre_init() {
    d_xpre1[blockIdx.x * Z1 + threadIdx.x] = d_lb1[threadIdx.x];
}

// ---------- K4: GEMM2 wmma NT, cp.async double-buffered, split-K z=4 ----------
__global__ __launch_bounds__(256) void k_gemm2() {
    extern __shared__ __align__(16) __nv_bfloat16 smb[];
    int bx = blockIdx.x, by = blockIdx.y, bz = blockIdx.z;
    int tid = threadIdx.x, warp = tid >> 5, lane = tid & 31;
    int wm = warp >> 1, wn = warp & 1;

    wmma::fragment<wmma::accumulator, 16, 16, 16, float> acc[2][2];
#pragma unroll
    for (int i = 0; i < 2; i++)
#pragma unroll
        for (int j = 0; j < 2; j++) wmma::fill_fragment(acc[i][j], 0.0f);

    const __nv_bfloat16* Agh = d_seqh + (long)(by * 128) * NC2;
    const __nv_bfloat16* Agl = d_seql + (long)(by * 128) * NC2;
    const __nv_bfloat16* Bgh = d_wihh + (long)(bx * 64) * NC2;
    const __nv_bfloat16* Bgl = d_wihl + (long)(bx * 64) * NC2;
    int kbase = bz * (NC2 / 4);
    const int NCH = (NC2 / 4) / 64;   // 66

    auto load_chunk = [&](int k0, int b) {
        __nv_bfloat16* Ah = smb + b * G1BUF;
        __nv_bfloat16* Al = Ah + 128 * 72;
        __nv_bfloat16* Bh = Al + 128 * 72;
        __nv_bfloat16* Bl = Bh + 64 * 72;
#pragma unroll
        for (int i = 0; i < 4; i++) {
            int idx = tid + i * 256;
            int row = idx >> 3, c8 = (idx & 7) * 8;
            cpa16(&Ah[row * 72 + c8], &Agh[(long)row * NC2 + k0 + c8]);
            cpa16(&Al[row * 72 + c8], &Agl[(long)row * NC2 + k0 + c8]);
        }
#pragma unroll
        for (int i = 0; i < 2; i++) {
            int idx = tid + i * 256;
            int nr = idx >> 3, c8 = (idx & 7) * 8;
            cpa16(&Bh[nr * 72 + c8], &Bgh[(long)nr * NC2 + k0 + c8]);
            cpa16(&Bl[nr * 72 + c8], &Bgl[(long)nr * NC2 + k0 + c8]);
        }
        cpa_commit();
    };

    load_chunk(kbase, 0);
    for (int ch = 0; ch < NCH; ch++) {
        int p = ch & 1;
        if (ch + 1 < NCH) load_chunk(kbase + (ch + 1) * 64, p ^ 1);
        if (ch + 1 < NCH) asm volatile("cp.async.wait_group 1;");
        else              asm volatile("cp.async.wait_group 0;");
        __syncthreads();
        __nv_bfloat16* Ah = smb + p * G1BUF;
        __nv_bfloat16* Al = Ah + 128 * 72;
        __nv_bfloat16* Bh = Al + 128 * 72;
        __nv_bfloat16* Bl = Bh + 64 * 72;
#pragma unroll
        for (int k16 = 0; k16 < 4; k16++) {
            wmma::fragment<wmma::matrix_a, 16, 16, 16, __nv_bfloat16, wmma::row_major> ah[2], al[2];
#pragma unroll
            for (int i = 0; i < 2; i++) {
                wmma::load_matrix_sync(ah[i], Ah + (wm * 32 + i * 16) * 72 + k16 * 16, 72);
                wmma::load_matrix_sync(al[i], Al + (wm * 32 + i * 16) * 72 + k16 * 16, 72);
            }
            wmma::fragment<wmma::matrix_b, 16, 16, 16, __nv_bfloat16, wmma::col_major> bh[2], bl[2];
#pragma unroll
            for (int j = 0; j < 2; j++) {
                wmma::load_matrix_sync(bh[j], Bh + (wn * 32 + j * 16) * 72 + k16 * 16, 72);
                wmma::load_matrix_sync(bl[j], Bl + (wn * 32 + j * 16) * 72 + k16 * 16, 72);
            }
#pragma unroll
            for (int i = 0; i < 2; i++)
#pragma unroll
                for (int j = 0; j < 2; j++) {
                    wmma::mma_sync(acc[i][j], ah[i], bh[j], acc[i][j]);
                    wmma::mma_sync(acc[i][j], ah[i], bl[j], acc[i][j]);
                    wmma::mma_sync(acc[i][j], al[i], bh[j], acc[i][j]);
                }
        }
        __syncthreads();
    }
    float* stage = (float*)smb;
    float* ws = stage + warp * (32 * 36);
#pragma unroll
    for (int i = 0; i < 2; i++)
#pragma unroll
        for (int j = 0; j < 2; j++)
            wmma::store_matrix_sync(ws + i * 16 * 36 + j * 16, acc[i][j], 36, wmma::mem_row_major);
    __syncwarp();
    int m0 = by * 128 + wm * 32;
    int n0 = bx * 64 + wn * 32;
    for (int k = 0; k < 32; k++)
        atomicAdd(&d_xpre1[(m0 + k) * Z1 + n0 + lane], ws[k * 36 + lane]);
}

// ---------- K5: LSTM1 ----------
__global__ __launch_bounds__(512, 1) void k_lstm1(const float* __restrict__ whh) {
    int j = threadIdx.x;
    extern __shared__ float sm[];
    float* sw  = sm;
    float* hsm = sw + (WSM / 4) * 512 * 4;
    float* zsm = hsm + 128;

    ull wd[WREG / 2];
#pragma unroll
    for (int q4 = 0; q4 < WREG / 4; q4++) {
        ulonglong2 v = *(const ulonglong2*)(whh + j * HID1 + 4 * q4);
        wd[2 * q4] = v.x; wd[2 * q4 + 1] = v.y;
    }
#pragma unroll
    for (int kk4 = 0; kk4 < WSM / 4; kk4++)
        ((float4*)sw)[kk4 * 512 + j] = *(const float4*)(whh + j * HID1 + WREG + kk4 * 4);
    if (j < HID1) hsm[j] = 0.0f;
    float c = 0.0f;
    int gate = j >> 7;
    __syncthreads();

    const ulonglong2* h2 = (const ulonglong2*)hsm;
    const ulonglong2* sw2 = (const ulonglong2*)sw;
    float xv = d_xpre1[j];
    for (int t = 0; t < TT; t++) {
        ull pa = pk2(xv, 0.0f), pb = 0ull;
#pragma unroll
        for (int q4 = 0; q4 < WREG / 4; q4++) {
            ulonglong2 hv = h2[q4];
            pa = ffma2(wd[2 * q4],     hv.x, pa);
            pb = ffma2(wd[2 * q4 + 1], hv.y, pb);
        }
#pragma unroll
        for (int kk4 = 0; kk4 < WSM / 4; kk4++) {
            ulonglong2 w = sw2[kk4 * 512 + j];
            ulonglong2 hv = h2[WREG / 4 + kk4];
            pa = ffma2(w.x, hv.x, pa);
            pb = ffma2(w.y, hv.y, pb);
        }
        float2 fa = upk2(pa), fb = upk2(pb);
        float z = (fa.x + fb.x) + (fa.y + fb.y);
        zsm[j] = (gate == 2) ? tanhf(z) : sigm(z);
        if (t + 1 < TT) xv = d_xpre1[(t + 1) * Z1 + j];
        __syncthreads();
        if (j < HID1) {
            float ai = zsm[j], af = zsm[HID1 + j], ag = zsm[2 * HID1 + j], ao = zsm[3 * HID1 + j];
            c = af * c + ai * ag;
            float h = ao * tanhf(c);
            hsm[j] = h;
            d_hs1[t * HID1 + j] = h;
        }
        __syncthreads();
    }
}

// ---------- K6: xpre2 ----------
__global__ __launch_bounds__(256) void k_xpre2(const float* __restrict__ wih2) {
    int t = blockIdx.x;
    int tid = threadIdx.x;
    __shared__ __align__(16) float h[HID1];
    if (tid < HID1) h[tid] = d_hs1[t * HID1 + tid];
    __syncthreads();
    const ulonglong2* w2 = (const ulonglong2*)(wih2 + tid * HID1);
    const ulonglong2* h2 = (const ulonglong2*)h;
    ull pa = 0ull, pb = 0ull;
#pragma unroll
    for (int q4 = 0; q4 < HID1 / 4; q4++) {
        ulonglong2 w = w2[q4], hv = h2[q4];
        pa = ffma2(w.x, hv.x, pa);
        pb = ffma2(w.y, hv.y, pb);
    }
    float2 fa = upk2(pa), fb = upk2(pb);
    d_xpre2[t * Z2 + tid] = (fa.x + fb.x) + (fa.y + fb.y) + d_lb2[tid];
}

// ---------- K7: LSTM2 + FC ----------
__global__ __launch_bounds__(256, 1) void k_lstm2(const float* __restrict__ whh2,
                                                  const float* __restrict__ fcw,
                                                  const float* __restrict__ fcb,
                                                  float* __restrict__ out) {
    int j = threadIdx.x;
    __shared__ __align__(16) float hsm[HID2];
    __shared__ float zsm[Z2];
    ull wd[HID2 / 2];
#pragma unroll
    for (int q4 = 0; q4 < HID2 / 4; q4++) {
        ulonglong2 v = *(const ulonglong2*)(whh2 + j * HID2 + 4 * q4);
        wd[2 * q4] = v.x; wd[2 * q4 + 1] = v.y;
    }
    if (j < HID2) hsm[j] = 0.0f;
    float c = 0.0f;
    int gate = j >> 6;
    __syncthreads();
    const ulonglong2* h2 = (const ulonglong2*)hsm;
    float xv = d_xpre2[j];
    for (int t = 0; t < TT; t++) {
        ull pa = pk2(xv, 0.0f), pb = 0ull;
#pragma unroll
        for (int q4 = 0; q4 < HID2 / 4; q4++) {
            ulonglong2 hv = h2[q4];
            pa = ffma2(wd[2 * q4],     hv.x, pa);
            pb = ffma2(wd[2 * q4 + 1], hv.y, pb);
        }
        float2 fa = upk2(pa), fb = upk2(pb);
        float z = (fa.x + fb.x) + (fa.y + fb.y);
        zsm[j] = (gate == 2) ? tanhf(z) : sigm(z);
        if (t + 1 < TT) xv = d_xpre2[(t + 1) * Z2 + j];
        __syncthreads();
        if (j < HID2) {
            float ai = zsm[j], af = zsm[HID2 + j], ag = zsm[2 * HID2 + j], ao = zsm[3 * HID2 + j];
            c = af * c + ai * ag;
            hsm[j] = ao * tanhf(c);
        }
        __syncthreads();
    }
    if (j < 4) {
        float acc = fcb[j];
        for (int k = 0; k < HID2; k++) acc = fmaf(fcw[j * HID2 + k], hsm[k], acc);
        out[j] = acc;
    }
}

extern "C" void kernel_launch(void* const* d_in, const int* in_sizes, int n_in,
                              void* d_out, int out_size) {
    const float* x      = (const float*)d_in[0];
    const int*   ei     = (const int*)d_in[1];
    const float* ea     = (const float*)d_in[2];
    const float* g1_wl  = (const float*)d_in[3];
    const float* g1_wr  = (const float*)d_in[4];
    const float* g1_we  = (const float*)d_in[5];
    const float* g1_att = (const float*)d_in[6];
    const float* g1_b   = (const float*)d_in[7];
    const float* g2_wl  = (const float*)d_in[8];
    const float* g2_wr  = (const float*)d_in[9];
    const float* g2_we  = (const float*)d_in[10];
    const float* g2_att = (const float*)d_in[11];
    const float* g2_b   = (const float*)d_in[12];
    const float* l1_wih = (const float*)d_in[13];
    const float* l1_whh = (const float*)d_in[14];
    const float* l1_bih = (const float*)d_in[15];
    const float* l1_bhh = (const float*)d_in[16];
    const float* l2_wih = (const float*)d_in[17];
    const float* l2_whh = (const float*)d_in[18];
    const float* l2_bih = (const float*)d_in[19];
    const float* l2_bhh = (const float*)d_in[20];
    const float* fc_w   = (const float*)d_in[21];
    const float* fc_b   = (const float*)d_in[22];
    float* out = (float*)d_out;

    const int SMEM_GAT1  = (16896 + 1552 + 776 + 776 + 68) * 4 + 325 * 4;
    const int SMEM_GAT2  = (16896 + 1552 + 104 + 104) * 4 + 325 * 4;
    const int SMEM_LSTM1 = ((WSM / 4) * 512 * 4 + 128 + 512) * 4;
    const int SMEM_GEMM  = G1BUF * 2 * 2 * 2;   // 2 buffers * 27648 elems * 2B = 110592
    cudaFuncSetAttribute(k_gat1, cudaFuncAttributeMaxDynamicSharedMemorySize, SMEM_GAT1);
    cudaFuncSetAttribute(k_gat2, cudaFuncAttributeMaxDynamicSharedMemorySize, SMEM_GAT2);
    cudaFuncSetAttribute(k_lstm1, cudaFuncAttributeMaxDynamicSharedMemorySize, SMEM_LSTM1);
    cudaFuncSetAttribute(k_gemm1, cudaFuncAttributeMaxDynamicSharedMemorySize, SMEM_GEMM);
    cudaFuncSetAttribute(k_gemm2, cudaFuncAttributeMaxDynamicSharedMemorySize, SMEM_GEMM);

    k_setup<<<1, 512>>>(ei, ea, g1_we, g2_we, l1_bih, l1_bhh, l2_bih, l2_bhh);
    k_split_w1<<<512, 256>>>(g2_wl, g2_wr);
    k_split_w2<<<512, 256>>>(l1_wih);
    k_gat1<<<TT, 512, SMEM_GAT1>>>(x, g1_wl, g1_wr, g1_att, g1_b);
    k_gemm1<<<dim3(16, 264), 256, SMEM_GEMM>>>();
    k_gat2<<<TT, 512, SMEM_GAT2>>>(g2_att, g2_b);
    k_xpre_init<<<TT, Z1>>>();
    k_gemm2<<<dim3(8, 8, 4), 256, SMEM_GEMM>>>();
    k_lstm1<<<1, 512, SMEM_LSTM1>>>(l1_whh);
    k_xpre2<<<TT, 256>>>(l2_wih);
    k_lstm2<<<1, 256>>>(l2_whh, fc_w, fc_b, out);
}

// round 11
// speedup vs baseline: 1.0230x; 1.0230x over previous
#include <cuda_runtime.h>
#include <cuda_bf16.h>
#include <mma.h>
#include <math.h>

using namespace nvcuda;

#define NN 33
#define TT 1024
#define EE 97
#define H1 8
#define HC 512
#define C2 512
#define HID1 128
#define Z1 512
#define NC2 16896
#define HID2 64
#define Z2 256
#define WREG 96
#define WSM  32   // WREG + WSM == HID1

typedef unsigned long long ull;

__device__ float d_ep1[EE * HC];
__device__ float d_ep2[EE * C2];
__device__ int   d_csr_start[NN + 1];
__device__ int   d_csr_eid[EE];
__device__ int   d_src[EE];
__device__ int   d_dst[EE];
__device__ __align__(16) __nv_bfloat16 d_h1hi[TT * NN * HC];
__device__ __align__(16) __nv_bfloat16 d_h1lo[TT * NN * HC];
__device__ __align__(16) __nv_bfloat16 d_g2bhi[512 * 1024];
__device__ __align__(16) __nv_bfloat16 d_g2blo[512 * 1024];
__device__ __align__(16) __nv_bfloat16 d_seqh[NN * TT * C2];
__device__ __align__(16) __nv_bfloat16 d_seql[NN * TT * C2];
__device__ __align__(16) __nv_bfloat16 d_wihh[(long)Z1 * NC2];
__device__ __align__(16) __nv_bfloat16 d_wihl[(long)Z1 * NC2];
__device__ float d_hl[TT * NN * C2];
__device__ float d_hr[TT * NN * C2];
__device__ float d_xpre1[TT * Z1];
__device__ float d_hs1[TT * HID1];
__device__ float d_xpre2[TT * Z2];
__device__ float d_lb1[Z1];
__device__ float d_lb2[Z2];

__device__ __forceinline__ float fsigm(float x) {
    return __fdividef(1.0f, 1.0f + __expf(-x));
}
__device__ __forceinline__ float ftanh(float x) {
    float e = __expf(2.0f * x);
    return 1.0f - __fdividef(2.0f, e + 1.0f);
}
__device__ __forceinline__ float sigm(float x) { return 1.0f / (1.0f + expf(-x)); }

__device__ __forceinline__ ull ffma2(ull a, ull b, ull c) {
    ull d;
    asm("fma.rn.f32x2 %0, %1, %2, %3;" : "=l"(d) : "l"(a), "l"(b), "l"(c));
    return d;
}
__device__ __forceinline__ ull pk2(float lo, float hi) {
    ull r;
    asm("mov.b64 %0, {%1, %2};" : "=l"(r) : "f"(lo), "f"(hi));
    return r;
}
__device__ __forceinline__ float2 upk2(ull v) {
    float2 f;
    asm("mov.b64 {%0, %1}, %2;" : "=f"(f.x), "=f"(f.y) : "l"(v));
    return f;
}

// ---------- K0: setup ----------
__global__ __launch_bounds__(512) void k_setup(const int* __restrict__ ei, const float* __restrict__ ea,
                        const float* __restrict__ g1_we, const float* __restrict__ g2_we,
                        const float* __restrict__ b1i, const float* __restrict__ b1h,
                        const float* __restrict__ b2i, const float* __restrict__ b2h) {
    __shared__ int cnt[NN + 1];
    __shared__ int pos[NN];
    int tid = threadIdx.x;
    if (tid == 0) {
        for (int n = 0; n <= NN; n++) cnt[n] = 0;
        for (int e = 0; e < EE; e++) {
            d_src[e] = ei[e];
            d_dst[e] = ei[EE + e];
            cnt[ei[EE + e] + 1]++;
        }
        for (int n = 0; n < NN; n++) cnt[n + 1] += cnt[n];
        for (int n = 0; n <= NN; n++) d_csr_start[n] = cnt[n];
        for (int n = 0; n < NN; n++) pos[n] = cnt[n];
        for (int e = 0; e < EE; e++) d_csr_eid[pos[ei[EE + e]]++] = e;
    }
    for (int e = 0; e < EE; e++) {
        float a0 = ea[e * 3], a1 = ea[e * 3 + 1], a2 = ea[e * 3 + 2];
        d_ep1[e * HC + tid] = a0 * g1_we[tid] + a1 * g1_we[HC + tid] + a2 * g1_we[2 * HC + tid];
        d_ep2[e * C2 + tid] = a0 * g2_we[tid] + a1 * g2_we[C2 + tid] + a2 * g2_we[2 * C2 + tid];
    }
    d_lb1[tid] = b1i[tid] + b1h[tid];
    if (tid < Z2) d_lb2[tid] = b2i[tid] + b2h[tid];
}

// ---------- K0b: split gemm1 B into bf16 hi/lo ----------
__global__ __launch_bounds__(256) void k_split_w1(const float* __restrict__ wl,
                                                  const float* __restrict__ wr) {
    int k = blockIdx.x;
    for (int n = threadIdx.x; n < 1024; n += 256) {
        float v = (n < 512) ? wl[k * 512 + n] : wr[k * 512 + (n - 512)];
        __nv_bfloat16 hi = __float2bfloat16(v);
        d_g2bhi[k * 1024 + n] = hi;
        d_g2blo[k * 1024 + n] = __float2bfloat16(v - __bfloat162float(hi));
    }
}

// ---------- K0c: split l1_wih into bf16 hi/lo ----------
__global__ __launch_bounds__(256) void k_split_w2(const float* __restrict__ w) {
    int n = blockIdx.x;
    for (int k = threadIdx.x; k < NC2; k += 256) {
        float v = w[(long)n * NC2 + k];
        __nv_bfloat16 hi = __float2bfloat16(v);
        d_wihh[(long)n * NC2 + k] = hi;
        d_wihl[(long)n * NC2 + k] = __float2bfloat16(v - __bfloat162float(hi));
    }
}

// ---------- K1: GAT1 (epilogue writes bf16 split of h1) ----------
__global__ __launch_bounds__(512) void k_gat1(const float* __restrict__ x,
                                              const float* __restrict__ wl,
                                              const float* __restrict__ wr,
                                              const float* __restrict__ att,
                                              const float* __restrict__ bias) {
    int t = blockIdx.x;
    int tid = threadIdx.x;
    extern __shared__ float sm[];
    float* xl    = sm;            // 16896
    float* part  = xl + 16896;    // 97*16
    float* logit = part + 1552;   // 97*8
    float* alpha = logit + 776;   // 97*8
    float* sx    = alpha + 776;   // 68
    int* cstart = (int*)(sx + 68);
    int* ceid   = cstart + NN + 1;
    int* csrc   = ceid + EE;
    int* cdst   = csrc + EE;

    if (tid < 2 * NN) sx[tid] = x[t * (2 * NN) + tid];
    if (tid < NN + 1) cstart[tid] = d_csr_start[tid];
    if (tid < EE) { ceid[tid] = d_csr_eid[tid]; csrc[tid] = d_src[tid]; cdst[tid] = d_dst[tid]; }
    float wl0 = wl[tid], wl1 = wl[HC + tid];
    float wr0 = wr[tid], wr1 = wr[HC + tid];
    float attc = att[tid];
    __syncthreads();

    for (int n = 0; n < NN; n++)
        xl[n * HC + tid] = fmaf(sx[2 * n], wl0, sx[2 * n + 1] * wl1);
    __syncthreads();

    int lane = tid & 31, warp = tid >> 5;
#pragma unroll 4
    for (int e = 0; e < EE; e++) {
        int s = csrc[e], d = cdst[e];
        float xr = fmaf(sx[2 * d], wr0, sx[2 * d + 1] * wr1);
        float v = xl[s * HC + tid] + xr + d_ep1[e * HC + tid];
        v = fmaxf(v, 0.2f * v);
        v *= attc;
        v += __shfl_xor_sync(0xffffffffu, v, 16);
        v += __shfl_xor_sync(0xffffffffu, v, 8);
        v += __shfl_xor_sync(0xffffffffu, v, 4);
        v += __shfl_xor_sync(0xffffffffu, v, 2);
        v += __shfl_xor_sync(0xffffffffu, v, 1);
        if (lane == 0) part[e * 16 + warp] = v;
    }
    __syncthreads();
    for (int idx = tid; idx < EE * H1; idx += 512) {
        int e = idx >> 3, h = idx & 7;
        logit[idx] = part[e * 16 + 2 * h] + part[e * 16 + 2 * h + 1];
    }
    __syncthreads();
    for (int idx = tid; idx < NN * H1; idx += 512) {
        int n = idx >> 3, h = idx & 7;
        int s0 = cstart[n], s1 = cstart[n + 1];
        float m = -INFINITY;
        for (int p = s0; p < s1; p++) m = fmaxf(m, logit[ceid[p] * 8 + h]);
        float den = 0.0f;
        for (int p = s0; p < s1; p++) {
            float ex = expf(logit[ceid[p] * 8 + h] - m);
            den += ex;
            alpha[ceid[p] * 8 + h] = ex;
        }
        float inv = 1.0f / (den + 1e-16f);
        for (int p = s0; p < s1; p++) alpha[ceid[p] * 8 + h] *= inv;
    }
    __syncthreads();
    int h = tid >> 6;
    float b = bias[tid];
    for (int n = 0; n < NN; n++) {
        int s0 = cstart[n], s1 = cstart[n + 1];
        float acc = 0.0f;
        for (int p = s0; p < s1; p++) {
            int e = ceid[p];
            acc = fmaf(alpha[e * 8 + h], xl[csrc[e] * HC + tid], acc);
        }
        float o = acc + b;
        o = o > 0.0f ? o : expm1f(o);
        long idx = (long)(t * NN + n) * HC + tid;
        __nv_bfloat16 hi = __float2bfloat16(o);
        d_h1hi[idx] = hi;
        d_h1lo[idx] = __float2bfloat16(o - __bfloat162float(hi));
    }
}

// ---------- K2: GEMM1 wmma — 128x64, Kc=64, 8 warps, 3-MMA split (R9 best) ----------
__global__ __launch_bounds__(256) void k_gemm1() {
    extern __shared__ __align__(16) __nv_bfloat16 smb[];
    __nv_bfloat16* Ah = smb;                 // 128*72
    __nv_bfloat16* Al = Ah + 128 * 72;
    __nv_bfloat16* Bh = Al + 128 * 72;       // 64*72
    __nv_bfloat16* Bl = Bh + 64 * 72;
    int nt = blockIdx.x, mb = blockIdx.y;
    int tid = threadIdx.x, warp = tid >> 5;
    int wm = warp >> 1, wn = warp & 1;

    wmma::fragment<wmma::accumulator, 16, 16, 16, float> acc[2][2];
#pragma unroll
    for (int i = 0; i < 2; i++)
#pragma unroll
        for (int j = 0; j < 2; j++) wmma::fill_fragment(acc[i][j], 0.0f);

    const __nv_bfloat16* Agh = d_h1hi + (long)(mb * 128) * 512;
    const __nv_bfloat16* Agl = d_h1lo + (long)(mb * 128) * 512;

    for (int k0 = 0; k0 < 512; k0 += 64) {
#pragma unroll
        for (int i = 0; i < 4; i++) {
            int idx = tid + i * 256;
            int row = idx >> 3, c8 = (idx & 7) * 8;
            *(int4*)&Ah[row * 72 + c8] = *(const int4*)&Agh[(long)row * 512 + k0 + c8];
            *(int4*)&Al[row * 72 + c8] = *(const int4*)&Agl[(long)row * 512 + k0 + c8];
        }
#pragma unroll
        for (int i = 0; i < 2; i++) {
            int idx = tid + i * 256;
            int kr = idx >> 3, c8 = (idx & 7) * 8;
            *(int4*)&Bh[kr * 72 + c8] = *(const int4*)&d_g2bhi[(k0 + kr) * 1024 + nt * 64 + c8];
            *(int4*)&Bl[kr * 72 + c8] = *(const int4*)&d_g2blo[(k0 + kr) * 1024 + nt * 64 + c8];
        }
        __syncthreads();
#pragma unroll
        for (int k16 = 0; k16 < 4; k16++) {
            wmma::fragment<wmma::matrix_a, 16, 16, 16, __nv_bfloat16, wmma::row_major> ah[2], al[2];
#pragma unroll
            for (int i = 0; i < 2; i++) {
                wmma::load_matrix_sync(ah[i], Ah + (wm * 32 + i * 16) * 72 + k16 * 16, 72);
                wmma::load_matrix_sync(al[i], Al + (wm * 32 + i * 16) * 72 + k16 * 16, 72);
            }
            wmma::fragment<wmma::matrix_b, 16, 16, 16, __nv_bfloat16, wmma::row_major> bh[2], bl[2];
#pragma unroll
            for (int j = 0; j < 2; j++) {
                wmma::load_matrix_sync(bh[j], Bh + (k16 * 16) * 72 + wn * 32 + j * 16, 72);
                wmma::load_matrix_sync(bl[j], Bl + (k16 * 16) * 72 + wn * 32 + j * 16, 72);
            }
#pragma unroll
            for (int i = 0; i < 2; i++)
#pragma unroll
                for (int j = 0; j < 2; j++) {
                    wmma::mma_sync(acc[i][j], ah[i], bh[j], acc[i][j]);
                    wmma::mma_sync(acc[i][j], ah[i], bl[j], acc[i][j]);
                    wmma::mma_sync(acc[i][j], al[i], bh[j], acc[i][j]);
                }
        }
        __syncthreads();
    }
    float* C = (nt < 8) ? d_hl : d_hr;
    int c0 = (nt & 7) * 64;
#pragma unroll
    for (int i = 0; i < 2; i++)
#pragma unroll
        for (int j = 0; j < 2; j++)
            wmma::store_matrix_sync(C + (long)(mb * 128 + wm * 32 + i * 16) * 512 + c0 + wn * 32 + j * 16,
                                    acc[i][j], 512, wmma::mem_row_major);
}

// ---------- K3: GAT2 (epilogue writes bf16 split of seq) ----------
__global__ __launch_bounds__(512) void k_gat2(const float* __restrict__ att2,
                                              const float* __restrict__ bias2) {
    int t = blockIdx.x;
    int tid = threadIdx.x;
    extern __shared__ float sm[];
    float* hl    = sm;           // 16896
    float* part  = hl + 16896;   // 1552
    float* logit = part + 1552;  // 104
    float* alpha = logit + 104;  // 104
    int* cstart = (int*)(alpha + 104);
    int* ceid   = cstart + NN + 1;
    int* csrc   = ceid + EE;
    int* cdst   = csrc + EE;

    const float4* srcl = (const float4*)(d_hl + (long)t * NC2);
    for (int i = tid; i < NC2 / 4; i += 512)
        ((float4*)hl)[i] = srcl[i];
    if (tid < NN + 1) cstart[tid] = d_csr_start[tid];
    if (tid < EE) { ceid[tid] = d_csr_eid[tid]; csrc[tid] = d_src[tid]; cdst[tid] = d_dst[tid]; }
    float attc = att2[tid];
    float b = bias2[tid];
    const float* hrg = d_hr + (long)t * NC2;
    __syncthreads();

    int lane = tid & 31, warp = tid >> 5;
#pragma unroll 4
    for (int e = 0; e < EE; e++) {
        int s = csrc[e], d = cdst[e];
        float v = hl[s * C2 + tid] + __ldg(hrg + d * C2 + tid) + __ldg(&d_ep2[e * C2 + tid]);
        v = fmaxf(v, 0.2f * v);
        v *= attc;
        v += __shfl_xor_sync(0xffffffffu, v, 16);
        v += __shfl_xor_sync(0xffffffffu, v, 8);
        v += __shfl_xor_sync(0xffffffffu, v, 4);
        v += __shfl_xor_sync(0xffffffffu, v, 2);
        v += __shfl_xor_sync(0xffffffffu, v, 1);
        if (lane == 0) part[e * 16 + warp] = v;
    }
    __syncthreads();
    if (tid < EE) {
        float s = 0.0f;
        for (int w = 0; w < 16; w++) s += part[tid * 16 + w];
        logit[tid] = s;
    }
    __syncthreads();
    if (tid < NN) {
        int s0 = cstart[tid], s1 = cstart[tid + 1];
        float m = -INFINITY;
        for (int p = s0; p < s1; p++) m = fmaxf(m, logit[ceid[p]]);
        float den = 0.0f;
        for (int p = s0; p < s1; p++) {
            float ex = expf(logit[ceid[p]] - m);
            den += ex;
            alpha[ceid[p]] = ex;
        }
        float inv = 1.0f / (den + 1e-16f);
        for (int p = s0; p < s1; p++) alpha[ceid[p]] *= inv;
    }
    __syncthreads();
    for (int n = 0; n < NN; n++) {
        int s0 = cstart[n], s1 = cstart[n + 1];
        float acc = 0.0f;
        for (int p = s0; p < s1; p++) {
            int e = ceid[p];
            acc = fmaf(alpha[e], hl[csrc[e] * C2 + tid], acc);
        }
        float o = acc + b;
        o = o > 0.0f ? o : expm1f(o);
        long idx = ((long)n * TT + t) * C2 + tid;
        __nv_bfloat16 hi = __float2bfloat16(o);
        d_seqh[idx] = hi;
        d_seql[idx] = __float2bfloat16(o - __bfloat162float(hi));
    }
}

// ---------- K4a: init xpre1 with biases ----------
__global__ __launch_bounds__(512) void k_xpre_init() {
    d_xpre1[blockIdx.x * Z1 + threadIdx.x] = d_lb1[threadIdx.x];
}

// ---------- K4: GEMM2 wmma NT, split-K z=4, atomic epilogue (R9 best) ----------
__global__ __launch_bounds__(256) void k_gemm2() {
    extern __shared__ __align__(16) __nv_bfloat16 smb[];
    __nv_bfloat16* Ah = smb;                 // 128*72
    __nv_bfloat16* Al = Ah + 128 * 72;
    __nv_bfloat16* Bh = Al + 128 * 72;       // 64 n x 72 k
    __nv_bfloat16* Bl = Bh + 64 * 72;
    int bx = blockIdx.x, by = blockIdx.y, bz = blockIdx.z;
    int tid = threadIdx.x, warp = tid >> 5, lane = tid & 31;
    int wm = warp >> 1, wn = warp & 1;

    wmma::fragment<wmma::accumulator, 16, 16, 16, float> acc[2][2];
#pragma unroll
    for (int i = 0; i < 2; i++)
#pragma unroll
        for (int j = 0; j < 2; j++) wmma::fill_fragment(acc[i][j], 0.0f);

    const __nv_bfloat16* Agh = d_seqh + (long)(by * 128) * NC2;
    const __nv_bfloat16* Agl = d_seql + (long)(by * 128) * NC2;
    const __nv_bfloat16* Bgh = d_wihh + (long)(bx * 64) * NC2;
    const __nv_bfloat16* Bgl = d_wihl + (long)(bx * 64) * NC2;

    int kbase = bz * (NC2 / 4);
    for (int ch = 0; ch < (NC2 / 4) / 64; ch++) {
        int k0 = kbase + ch * 64;
#pragma unroll
        for (int i = 0; i < 4; i++) {
            int idx = tid + i * 256;
            int row = idx >> 3, c8 = (idx & 7) * 8;
            *(int4*)&Ah[row * 72 + c8] = *(const int4*)&Agh[(long)row * NC2 + k0 + c8];
            *(int4*)&Al[row * 72 + c8] = *(const int4*)&Agl[(long)row * NC2 + k0 + c8];
        }
#pragma unroll
        for (int i = 0; i < 2; i++) {
            int idx = tid + i * 256;
            int nr = idx >> 3, c8 = (idx & 7) * 8;
            *(int4*)&Bh[nr * 72 + c8] = *(const int4*)&Bgh[(long)nr * NC2 + k0 + c8];
            *(int4*)&Bl[nr * 72 + c8] = *(const int4*)&Bgl[(long)nr * NC2 + k0 + c8];
        }
        __syncthreads();
#pragma unroll
        for (int k16 = 0; k16 < 4; k16++) {
            wmma::fragment<wmma::matrix_a, 16, 16, 16, __nv_bfloat16, wmma::row_major> ah[2], al[2];
#pragma unroll
            for (int i = 0; i < 2; i++) {
                wmma::load_matrix_sync(ah[i], Ah + (wm * 32 + i * 16) * 72 + k16 * 16, 72);
                wmma::load_matrix_sync(al[i], Al + (wm * 32 + i * 16) * 72 + k16 * 16, 72);
            }
            wmma::fragment<wmma::matrix_b, 16, 16, 16, __nv_bfloat16, wmma::col_major> bh[2], bl[2];
#pragma unroll
            for (int j = 0; j < 2; j++) {
                wmma::load_matrix_sync(bh[j], Bh + (wn * 32 + j * 16) * 72 + k16 * 16, 72);
                wmma::load_matrix_sync(bl[j], Bl + (wn * 32 + j * 16) * 72 + k16 * 16, 72);
            }
#pragma unroll
            for (int i = 0; i < 2; i++)
#pragma unroll
                for (int j = 0; j < 2; j++) {
                    wmma::mma_sync(acc[i][j], ah[i], bh[j], acc[i][j]);
                    wmma::mma_sync(acc[i][j], ah[i], bl[j], acc[i][j]);
                    wmma::mma_sync(acc[i][j], al[i], bh[j], acc[i][j]);
                }
        }
        __syncthreads();
    }
    float* stage = (float*)smb;
    float* ws = stage + warp * (32 * 36);
#pragma unroll
    for (int i = 0; i < 2; i++)
#pragma unroll
        for (int j = 0; j < 2; j++)
            wmma::store_matrix_sync(ws + i * 16 * 36 + j * 16, acc[i][j], 36, wmma::mem_row_major);
    __syncwarp();
    int m0 = by * 128 + wm * 32;
    int n0 = bx * 64 + wn * 32;
    for (int k = 0; k < 32; k++)
        atomicAdd(&d_xpre1[(m0 + k) * Z1 + n0 + lane], ws[k * 36 + lane]);
}

// ---------- K5: LSTM1 — replicated-group update, group barriers, fast activations ----------
__global__ __launch_bounds__(512, 1) void k_lstm1(const float* __restrict__ whh) {
    int j = threadIdx.x;
    int jj = j & 127;
    int grp = j >> 7;
    extern __shared__ float sm[];
    float* sw   = sm;                          // (WSM/4)*512*4 = 16384 floats
    float* hsm4 = sw + (WSM / 4) * 512 * 4;    // 4 copies x 128
    float* zs0  = hsm4 + 512;                  // 512
    float* zs1  = zs0 + 512;                   // 512

    ull wd[WREG / 2];
#pragma unroll
    for (int q4 = 0; q4 < WREG / 4; q4++) {
        ulonglong2 v = *(const ulonglong2*)(whh + j * HID1 + 4 * q4);
        wd[2 * q4] = v.x; wd[2 * q4 + 1] = v.y;
    }
#pragma unroll
    for (int kk4 = 0; kk4 < WSM / 4; kk4++)
        ((float4*)sw)[kk4 * 512 + j] = *(const float4*)(whh + j * HID1 + WREG + kk4 * 4);
    hsm4[j] = 0.0f;   // grp*128 + jj == j
    float c = 0.0f;
    __syncthreads();

    const ulonglong2* h2 = (const ulonglong2*)(hsm4 + grp * 128);
    const ulonglong2* sw2 = (const ulonglong2*)sw;
    float xv = d_xpre1[j];
    for (int t = 0; t < TT; t++) {
        ull pa = pk2(xv, 0.0f), pb = 0ull;
#pragma unroll
        for (int q4 = 0; q4 < WREG / 4; q4++) {
            ulonglong2 hv = h2[q4];
            pa = ffma2(wd[2 * q4],     hv.x, pa);
            pb = ffma2(wd[2 * q4 + 1], hv.y, pb);
        }
#pragma unroll
        for (int kk4 = 0; kk4 < WSM / 4; kk4++) {
            ulonglong2 w = sw2[kk4 * 512 + j];
            ulonglong2 hv = h2[WREG / 4 + kk4];
            pa = ffma2(w.x, hv.x, pa);
            pb = ffma2(w.y, hv.y, pb);
        }
        float2 fa = upk2(pa), fb = upk2(pb);
        float z = (fa.x + fb.x) + (fa.y + fb.y);
        float* zw = (t & 1) ? zs1 : zs0;
        zw[j] = (grp == 2) ? ftanh(z) : fsigm(z);
        if (t + 1 < TT) xv = d_xpre1[(t + 1) * Z1 + j];
        __syncthreads();
        // all 512 threads compute the identical cell update for their jj
        float ai = zw[jj], af = zw[128 + jj], ag = zw[256 + jj], ao = zw[384 + jj];
        c = af * c + ai * ag;
        float h = ao * ftanh(c);
        hsm4[j] = h;                       // own group's copy
        if (grp == 0) d_hs1[t * HID1 + jj] = h;
        asm volatile("bar.sync %0, 128;" :: "r"(1 + grp) : "memory");
    }
}

// ---------- K6: xpre2 ----------
__global__ __launch_bounds__(256) void k_xpre2(const float* __restrict__ wih2) {
    int t = blockIdx.x;
    int tid = threadIdx.x;
    __shared__ __align__(16) float h[HID1];
    if (tid < HID1) h[tid] = d_hs1[t * HID1 + tid];
    __syncthreads();
    const ulonglong2* w2 = (const ulonglong2*)(wih2 + tid * HID1);
    const ulonglong2* h2 = (const ulonglong2*)h;
    ull pa = 0ull, pb = 0ull;
#pragma unroll
    for (int q4 = 0; q4 < HID1 / 4; q4++) {
        ulonglong2 w = w2[q4], hv = h2[q4];
        pa = ffma2(w.x, hv.x, pa);
        pb = ffma2(w.y, hv.y, pb);
    }
    float2 fa = upk2(pa), fb = upk2(pb);
    d_xpre2[t * Z2 + tid] = (fa.x + fb.x) + (fa.y + fb.y) + d_lb2[tid];
}

// ---------- K7: LSTM2 + FC — replicated-group update ----------
__global__ __launch_bounds__(256, 1) void k_lstm2(const float* __restrict__ whh2,
                                                  const float* __restrict__ fcw,
                                                  const float* __restrict__ fcb,
                                                  float* __restrict__ out) {
    int j = threadIdx.x;
    int jj = j & 63;
    int grp = j >> 6;
    __shared__ __align__(16) float hsm4[256];   // 4 copies x 64
    __shared__ float zs0[Z2];
    __shared__ float zs1[Z2];
    ull wd[HID2 / 2];
#pragma unroll
    for (int q4 = 0; q4 < HID2 / 4; q4++) {
        ulonglong2 v = *(const ulonglong2*)(whh2 + j * HID2 + 4 * q4);
        wd[2 * q4] = v.x; wd[2 * q4 + 1] = v.y;
    }
    hsm4[j] = 0.0f;
    float c = 0.0f;
    __syncthreads();
    const ulonglong2* h2 = (const ulonglong2*)(hsm4 + grp * 64);
    float xv = d_xpre2[j];
    for (int t = 0; t < TT; t++) {
        ull pa = pk2(xv, 0.0f), pb = 0ull;
#pragma unroll
        for (int q4 = 0; q4 < HID2 / 4; q4++) {
            ulonglong2 hv = h2[q4];
            pa = ffma2(wd[2 * q4],     hv.x, pa);
            pb = ffma2(wd[2 * q4 + 1], hv.y, pb);
        }
        float2 fa = upk2(pa), fb = upk2(pb);
        float z = (fa.x + fb.x) + (fa.y + fb.y);
        float* zw = (t & 1) ? zs1 : zs0;
        zw[j] = (grp == 2) ? ftanh(z) : fsigm(z);
        if (t + 1 < TT) xv = d_xpre2[(t + 1) * Z2 + j];
        __syncthreads();
        float ai = zw[jj], af = zw[64 + jj], ag = zw[128 + jj], ao = zw[192 + jj];
        c = af * c + ai * ag;
        hsm4[j] = ao * ftanh(c);
        asm volatile("bar.sync %0, 64;" :: "r"(1 + grp) : "memory");
    }
    if (j < 4) {
        float acc = fcb[j];
        for (int k = 0; k < HID2; k++) acc = fmaf(fcw[j * HID2 + k], hsm4[k], acc);
        out[j] = acc;
    }
}

extern "C" void kernel_launch(void* const* d_in, const int* in_sizes, int n_in,
                              void* d_out, int out_size) {
    const float* x      = (const float*)d_in[0];
    const int*   ei     = (const int*)d_in[1];
    const float* ea     = (const float*)d_in[2];
    const float* g1_wl  = (const float*)d_in[3];
    const float* g1_wr  = (const float*)d_in[4];
    const float* g1_we  = (const float*)d_in[5];
    const float* g1_att = (const float*)d_in[6];
    const float* g1_b   = (const float*)d_in[7];
    const float* g2_wl  = (const float*)d_in[8];
    const float* g2_wr  = (const float*)d_in[9];
    const float* g2_we  = (const float*)d_in[10];
    const float* g2_att = (const float*)d_in[11];
    const float* g2_b   = (const float*)d_in[12];
    const float* l1_wih = (const float*)d_in[13];
    const float* l1_whh = (const float*)d_in[14];
    const float* l1_bih = (const float*)d_in[15];
    const float* l1_bhh = (const float*)d_in[16];
    const float* l2_wih = (const float*)d_in[17];
    const float* l2_whh = (const float*)d_in[18];
    const float* l2_bih = (const float*)d_in[19];
    const float* l2_bhh = (const float*)d_in[20];
    const float* fc_w   = (const float*)d_in[21];
    const float* fc_b   = (const float*)d_in[22];
    float* out = (float*)d_out;

    const int SMEM_GAT1  = (16896 + 1552 + 776 + 776 + 68) * 4 + 325 * 4;
    const int SMEM_GAT2  = (16896 + 1552 + 104 + 104) * 4 + 325 * 4;
    const int SMEM_LSTM1 = ((WSM / 4) * 512 * 4 + 512 + 1024) * 4;
    const int SMEM_GEMM  = (128 * 72 * 2 + 64 * 72 * 2) * 2;   // 55296 bytes
    cudaFuncSetAttribute(k_gat1, cudaFuncAttributeMaxDynamicSharedMemorySize, SMEM_GAT1);
    cudaFuncSetAttribute(k_gat2, cudaFuncAttributeMaxDynamicSharedMemorySize, SMEM_GAT2);
    cudaFuncSetAttribute(k_lstm1, cudaFuncAttributeMaxDynamicSharedMemorySize, SMEM_LSTM1);
    cudaFuncSetAttribute(k_gemm1, cudaFuncAttributeMaxDynamicSharedMemorySize, SMEM_GEMM);
    cudaFuncSetAttribute(k_gemm2, cudaFuncAttributeMaxDynamicSharedMemorySize, SMEM_GEMM);

    k_setup<<<1, 512>>>(ei, ea, g1_we, g2_we, l1_bih, l1_bhh, l2_bih, l2_bhh);
    k_split_w1<<<512, 256>>>(g2_wl, g2_wr);
    k_split_w2<<<512, 256>>>(l1_wih);
    k_gat1<<<TT, 512, SMEM_GAT1>>>(x, g1_wl, g1_wr, g1_att, g1_b);
    k_gemm1<<<dim3(16, 264), 256, SMEM_GEMM>>>();
    k_gat2<<<TT, 512, SMEM_GAT2>>>(g2_att, g2_b);
    k_xpre_init<<<TT, Z1>>>();
    k_gemm2<<<dim3(8, 8, 4), 256, SMEM_GEMM>>>();
    k_lstm1<<<1, 512, SMEM_LSTM1>>>(l1_whh);
    k_xpre2<<<TT, 256>>>(l2_wih);
    k_lstm2<<<1, 256>>>(l2_whh, fc_w, fc_b, out);
}

// round 13
// speedup vs baseline: 1.0404x; 1.0171x over previous
#include <cuda_runtime.h>
#include <cuda_bf16.h>
#include <mma.h>
#include <math.h>

using namespace nvcuda;

#define NN 33
#define TT 1024
#define EE 97
#define H1 8
#define HC 512
#define C2 512
#define HID1 128
#define Z1 512
#define NC2 16896
#define HID2 64
#define Z2 256
#define WREG 96
#define WSM  32   // WREG + WSM == HID1

typedef unsigned long long ull;

__device__ float d_ep1[EE * HC];
__device__ float d_ep2[EE * C2];
__device__ int   d_csr_start[NN + 1];
__device__ int   d_csr_eid[EE];
__device__ int   d_src[EE];
__device__ int   d_dst[EE];
__device__ __align__(16) __nv_bfloat16 d_h1hi[TT * NN * HC];
__device__ __align__(16) __nv_bfloat16 d_h1lo[TT * NN * HC];
__device__ __align__(16) __nv_bfloat16 d_g2bhi[512 * 1024];
__device__ __align__(16) __nv_bfloat16 d_g2blo[512 * 1024];
__device__ __align__(16) __nv_bfloat16 d_seqh[NN * TT * C2];
__device__ __align__(16) __nv_bfloat16 d_seql[NN * TT * C2];
__device__ __align__(16) __nv_bfloat16 d_wihh[(long)Z1 * NC2];
__device__ __align__(16) __nv_bfloat16 d_wihl[(long)Z1 * NC2];
__device__ float d_hl[TT * NN * C2];
__device__ float d_hr[TT * NN * C2];
__device__ float d_xpre1[TT * Z1];
__device__ float d_hs1[TT * HID1];
__device__ float d_xpre2[TT * Z2];
__device__ float d_lb1[Z1];
__device__ float d_lb2[Z2];

__device__ __forceinline__ float fsigm(float x) {
    return __fdividef(1.0f, 1.0f + __expf(-x));
}
__device__ __forceinline__ float ftanh(float x) {
    float e = __expf(2.0f * x);
    return 1.0f - __fdividef(2.0f, e + 1.0f);
}

__device__ __forceinline__ ull ffma2(ull a, ull b, ull c) {
    ull d;
    asm("fma.rn.f32x2 %0, %1, %2, %3;" : "=l"(d) : "l"(a), "l"(b), "l"(c));
    return d;
}
__device__ __forceinline__ ull pk2(float lo, float hi) {
    ull r;
    asm("mov.b64 %0, {%1, %2};" : "=l"(r) : "f"(lo), "f"(hi));
    return r;
}
__device__ __forceinline__ float2 upk2(ull v) {
    float2 f;
    asm("mov.b64 {%0, %1}, %2;" : "=f"(f.x), "=f"(f.y) : "l"(v));
    return f;
}

// ---------- K0: setup ----------
__global__ __launch_bounds__(512) void k_setup(const int* __restrict__ ei, const float* __restrict__ ea,
                        const float* __restrict__ g1_we, const float* __restrict__ g2_we,
                        const float* __restrict__ b1i, const float* __restrict__ b1h,
                        const float* __restrict__ b2i, const float* __restrict__ b2h) {
    __shared__ int cnt[NN + 1];
    __shared__ int pos[NN];
    int tid = threadIdx.x;
    if (tid == 0) {
        for (int n = 0; n <= NN; n++) cnt[n] = 0;
        for (int e = 0; e < EE; e++) {
            d_src[e] = ei[e];
            d_dst[e] = ei[EE + e];
            cnt[ei[EE + e] + 1]++;
        }
        for (int n = 0; n < NN; n++) cnt[n + 1] += cnt[n];
        for (int n = 0; n <= NN; n++) d_csr_start[n] = cnt[n];
        for (int n = 0; n < NN; n++) pos[n] = cnt[n];
        for (int e = 0; e < EE; e++) d_csr_eid[pos[ei[EE + e]]++] = e;
    }
    for (int e = 0; e < EE; e++) {
        float a0 = ea[e * 3], a1 = ea[e * 3 + 1], a2 = ea[e * 3 + 2];
        d_ep1[e * HC + tid] = a0 * g1_we[tid] + a1 * g1_we[HC + tid] + a2 * g1_we[2 * HC + tid];
        d_ep2[e * C2 + tid] = a0 * g2_we[tid] + a1 * g2_we[C2 + tid] + a2 * g2_we[2 * C2 + tid];
    }
    d_lb1[tid] = b1i[tid] + b1h[tid];
    if (tid < Z2) d_lb2[tid] = b2i[tid] + b2h[tid];
}

// ---------- K0b: split gemm1 B into bf16 hi/lo ----------
__global__ __launch_bounds__(256) void k_split_w1(const float* __restrict__ wl,
                                                  const float* __restrict__ wr) {
    int k = blockIdx.x;
    for (int n = threadIdx.x; n < 1024; n += 256) {
        float v = (n < 512) ? wl[k * 512 + n] : wr[k * 512 + (n - 512)];
        __nv_bfloat16 hi = __float2bfloat16(v);
        d_g2bhi[k * 1024 + n] = hi;
        d_g2blo[k * 1024 + n] = __float2bfloat16(v - __bfloat162float(hi));
    }
}

// ---------- K0c: split l1_wih into bf16 hi/lo ----------
__global__ __launch_bounds__(256) void k_split_w2(const float* __restrict__ w) {
    int n = blockIdx.x;
    for (int k = threadIdx.x; k < NC2; k += 256) {
        float v = w[(long)n * NC2 + k];
        __nv_bfloat16 hi = __float2bfloat16(v);
        d_wihh[(long)n * NC2 + k] = hi;
        d_wihl[(long)n * NC2 + k] = __float2bfloat16(v - __bfloat162float(hi));
    }
}

// ---------- K1: GAT1 — warp-parallel edge phase ----------
__global__ __launch_bounds__(512) void k_gat1(const float* __restrict__ x,
                                              const float* __restrict__ wl,
                                              const float* __restrict__ wr,
                                              const float* __restrict__ att,
                                              const float* __restrict__ bias) {
    int t = blockIdx.x;
    int tid = threadIdx.x;
    extern __shared__ float sm[];
    float* xl    = sm;            // 16896
    float* logit = xl + 16896;    // 97*8 (776)
    float* alpha = logit + 776;   // 776
    float* sx    = alpha + 776;   // 68
    int* cstart = (int*)(sx + 68);
    int* ceid   = cstart + NN + 1;
    int* csrc   = ceid + EE;
    int* cdst   = csrc + EE;

    int lane = tid & 31, warp = tid >> 5;
    int cb = lane * 16;

    if (tid < 2 * NN) sx[tid] = x[t * (2 * NN) + tid];
    if (tid < NN + 1) cstart[tid] = d_csr_start[tid];
    if (tid < EE) { ceid[tid] = d_csr_eid[tid]; csrc[tid] = d_src[tid]; cdst[tid] = d_dst[tid]; }
    float wl0 = wl[tid], wl1 = wl[HC + tid];

    // per-lane 16-channel constants for the edge phase
    float wr0v[16], wr1v[16], attv[16];
#pragma unroll
    for (int i4 = 0; i4 < 4; i4++) {
        float4 a  = *(const float4*)&wr[cb + 4 * i4];
        float4 b  = *(const float4*)&wr[HC + cb + 4 * i4];
        float4 av = *(const float4*)&att[cb + 4 * i4];
        wr0v[4*i4] = a.x; wr0v[4*i4+1] = a.y; wr0v[4*i4+2] = a.z; wr0v[4*i4+3] = a.w;
        wr1v[4*i4] = b.x; wr1v[4*i4+1] = b.y; wr1v[4*i4+2] = b.z; wr1v[4*i4+3] = b.w;
        attv[4*i4] = av.x; attv[4*i4+1] = av.y; attv[4*i4+2] = av.z; attv[4*i4+3] = av.w;
    }
    __syncthreads();

    for (int n = 0; n < NN; n++)
        xl[n * HC + tid] = fmaf(sx[2 * n], wl0, sx[2 * n + 1] * wl1);
    __syncthreads();

    // edge phase: warp w handles edges w, w+16, ...
    for (int e = warp; e < EE; e += 16) {
        int s = csrc[e], d = cdst[e];
        float sd0 = sx[2 * d], sd1 = sx[2 * d + 1];
        const float* xle = xl + s * HC + cb;
        const float* epe = d_ep1 + e * HC + cb;
        float partial = 0.0f;
#pragma unroll
        for (int i4 = 0; i4 < 4; i4++) {
            float4 xlv = *(const float4*)&xle[4 * i4];
            float4 epv = __ldg((const float4*)&epe[4 * i4]);
            float v0 = xlv.x + fmaf(sd0, wr0v[4*i4],   sd1 * wr1v[4*i4])   + epv.x;
            float v1 = xlv.y + fmaf(sd0, wr0v[4*i4+1], sd1 * wr1v[4*i4+1]) + epv.y;
            float v2 = xlv.z + fmaf(sd0, wr0v[4*i4+2], sd1 * wr1v[4*i4+2]) + epv.z;
            float v3 = xlv.w + fmaf(sd0, wr0v[4*i4+3], sd1 * wr1v[4*i4+3]) + epv.w;
            v0 = fmaxf(v0, 0.2f * v0);
            v1 = fmaxf(v1, 0.2f * v1);
            v2 = fmaxf(v2, 0.2f * v2);
            v3 = fmaxf(v3, 0.2f * v3);
            partial = fmaf(v0, attv[4*i4],   partial);
            partial = fmaf(v1, attv[4*i4+1], partial);
            partial = fmaf(v2, attv[4*i4+2], partial);
            partial = fmaf(v3, attv[4*i4+3], partial);
        }
        partial += __shfl_xor_sync(0xffffffffu, partial, 1);
        partial += __shfl_xor_sync(0xffffffffu, partial, 2);
        if ((lane & 3) == 0) logit[e * 8 + (lane >> 2)] = partial;
    }
    __syncthreads();
    for (int idx = tid; idx < NN * H1; idx += 512) {
        int n = idx >> 3, h = idx & 7;
        int s0 = cstart[n], s1 = cstart[n + 1];
        float m = -INFINITY;
        for (int p = s0; p < s1; p++) m = fmaxf(m, logit[ceid[p] * 8 + h]);
        float den = 0.0f;
        for (int p = s0; p < s1; p++) {
            float ex = expf(logit[ceid[p] * 8 + h] - m);
            den += ex;
            alpha[ceid[p] * 8 + h] = ex;
        }
        float inv = 1.0f / (den + 1e-16f);
        for (int p = s0; p < s1; p++) alpha[ceid[p] * 8 + h] *= inv;
    }
    __syncthreads();
    int h = tid >> 6;
    float b = bias[tid];
    for (int n = 0; n < NN; n++) {
        int s0 = cstart[n], s1 = cstart[n + 1];
        float acc = 0.0f;
        for (int p = s0; p < s1; p++) {
            int e = ceid[p];
            acc = fmaf(alpha[e * 8 + h], xl[csrc[e] * HC + tid], acc);
        }
        float o = acc + b;
        o = o > 0.0f ? o : expm1f(o);
        long idx = (long)(t * NN + n) * HC + tid;
        __nv_bfloat16 hi = __float2bfloat16(o);
        d_h1hi[idx] = hi;
        d_h1lo[idx] = __float2bfloat16(o - __bfloat162float(hi));
    }
}

// ---------- K2: GEMM1 wmma — 128x64, Kc=64, 8 warps, 3-MMA split ----------
__global__ __launch_bounds__(256) void k_gemm1() {
    extern __shared__ __align__(16) __nv_bfloat16 smb[];
    __nv_bfloat16* Ah = smb;
    __nv_bfloat16* Al = Ah + 128 * 72;
    __nv_bfloat16* Bh = Al + 128 * 72;
    __nv_bfloat16* Bl = Bh + 64 * 72;
    int nt = blockIdx.x, mb = blockIdx.y;
    int tid = threadIdx.x, warp = tid >> 5;
    int wm = warp >> 1, wn = warp & 1;

    wmma::fragment<wmma::accumulator, 16, 16, 16, float> acc[2][2];
#pragma unroll
    for (int i = 0; i < 2; i++)
#pragma unroll
        for (int j = 0; j < 2; j++) wmma::fill_fragment(acc[i][j], 0.0f);

    const __nv_bfloat16* Agh = d_h1hi + (long)(mb * 128) * 512;
    const __nv_bfloat16* Agl = d_h1lo + (long)(mb * 128) * 512;

    for (int k0 = 0; k0 < 512; k0 += 64) {
#pragma unroll
        for (int i = 0; i < 4; i++) {
            int idx = tid + i * 256;
            int row = idx >> 3, c8 = (idx & 7) * 8;
            *(int4*)&Ah[row * 72 + c8] = *(const int4*)&Agh[(long)row * 512 + k0 + c8];
            *(int4*)&Al[row * 72 + c8] = *(const int4*)&Agl[(long)row * 512 + k0 + c8];
        }
#pragma unroll
        for (int i = 0; i < 2; i++) {
            int idx = tid + i * 256;
            int kr = idx >> 3, c8 = (idx & 7) * 8;
            *(int4*)&Bh[kr * 72 + c8] = *(const int4*)&d_g2bhi[(k0 + kr) * 1024 + nt * 64 + c8];
            *(int4*)&Bl[kr * 72 + c8] = *(const int4*)&d_g2blo[(k0 + kr) * 1024 + nt * 64 + c8];
        }
        __syncthreads();
#pragma unroll
        for (int k16 = 0; k16 < 4; k16++) {
            wmma::fragment<wmma::matrix_a, 16, 16, 16, __nv_bfloat16, wmma::row_major> ah[2], al[2];
#pragma unroll
            for (int i = 0; i < 2; i++) {
                wmma::load_matrix_sync(ah[i], Ah + (wm * 32 + i * 16) * 72 + k16 * 16, 72);
                wmma::load_matrix_sync(al[i], Al + (wm * 32 + i * 16) * 72 + k16 * 16, 72);
            }
            wmma::fragment<wmma::matrix_b, 16, 16, 16, __nv_bfloat16, wmma::row_major> bh[2], bl[2];
#pragma unroll
            for (int j = 0; j < 2; j++) {
                wmma::load_matrix_sync(bh[j], Bh + (k16 * 16) * 72 + wn * 32 + j * 16, 72);
                wmma::load_matrix_sync(bl[j], Bl + (k16 * 16) * 72 + wn * 32 + j * 16, 72);
            }
#pragma unroll
            for (int i = 0; i < 2; i++)
#pragma unroll
                for (int j = 0; j < 2; j++) {
                    wmma::mma_sync(acc[i][j], ah[i], bh[j], acc[i][j]);
                    wmma::mma_sync(acc[i][j], ah[i], bl[j], acc[i][j]);
                    wmma::mma_sync(acc[i][j], al[i], bh[j], acc[i][j]);
                }
        }
        __syncthreads();
    }
    float* C = (nt < 8) ? d_hl : d_hr;
    int c0 = (nt & 7) * 64;
#pragma unroll
    for (int i = 0; i < 2; i++)
#pragma unroll
        for (int j = 0; j < 2; j++)
            wmma::store_matrix_sync(C + (long)(mb * 128 + wm * 32 + i * 16) * 512 + c0 + wn * 32 + j * 16,
                                    acc[i][j], 512, wmma::mem_row_major);
}

// ---------- K3: GAT2 — warp-parallel edge phase ----------
__global__ __launch_bounds__(512) void k_gat2(const float* __restrict__ att2,
                                              const float* __restrict__ bias2) {
    int t = blockIdx.x;
    int tid = threadIdx.x;
    extern __shared__ float sm[];
    float* hl    = sm;           // 16896
    float* logit = hl + 16896;   // 104
    float* alpha = logit + 104;  // 104
    int* cstart = (int*)(alpha + 104);
    int* ceid   = cstart + NN + 1;
    int* csrc   = ceid + EE;
    int* cdst   = csrc + EE;

    int lane = tid & 31, warp = tid >> 5;
    int cb = lane * 16;

    const float4* srcl = (const float4*)(d_hl + (long)t * NC2);
    for (int i = tid; i < NC2 / 4; i += 512)
        ((float4*)hl)[i] = srcl[i];
    if (tid < NN + 1) cstart[tid] = d_csr_start[tid];
    if (tid < EE) { ceid[tid] = d_csr_eid[tid]; csrc[tid] = d_src[tid]; cdst[tid] = d_dst[tid]; }
    float b = bias2[tid];
    const float* hrg = d_hr + (long)t * NC2;

    float attv[16];
#pragma unroll
    for (int i4 = 0; i4 < 4; i4++) {
        float4 av = *(const float4*)&att2[cb + 4 * i4];
        attv[4*i4] = av.x; attv[4*i4+1] = av.y; attv[4*i4+2] = av.z; attv[4*i4+3] = av.w;
    }
    __syncthreads();

    for (int e = warp; e < EE; e += 16) {
        int s = csrc[e], d = cdst[e];
        const float* hle = hl + s * C2 + cb;
        const float* hre = hrg + d * C2 + cb;
        const float* epe = d_ep2 + e * C2 + cb;
        float partial = 0.0f;
#pragma unroll
        for (int i4 = 0; i4 < 4; i4++) {
            float4 hlv = *(const float4*)&hle[4 * i4];
            float4 hrv = __ldg((const float4*)&hre[4 * i4]);
            float4 epv = __ldg((const float4*)&epe[4 * i4]);
            float v0 = hlv.x + hrv.x + epv.x;
            float v1 = hlv.y + hrv.y + epv.y;
            float v2 = hlv.z + hrv.z + epv.z;
            float v3 = hlv.w + hrv.w + epv.w;
            v0 = fmaxf(v0, 0.2f * v0);
            v1 = fmaxf(v1, 0.2f * v1);
            v2 = fmaxf(v2, 0.2f * v2);
            v3 = fmaxf(v3, 0.2f * v3);
            partial = fmaf(v0, attv[4*i4],   partial);
            partial = fmaf(v1, attv[4*i4+1], partial);
            partial = fmaf(v2, attv[4*i4+2], partial);
            partial = fmaf(v3, attv[4*i4+3], partial);
        }
        partial += __shfl_xor_sync(0xffffffffu, partial, 16);
        partial += __shfl_xor_sync(0xffffffffu, partial, 8);
        partial += __shfl_xor_sync(0xffffffffu, partial, 4);
        partial += __shfl_xor_sync(0xffffffffu, partial, 2);
        partial += __shfl_xor_sync(0xffffffffu, partial, 1);
        if (lane == 0) logit[e] = partial;
    }
    __syncthreads();
    if (tid < NN) {
        int s0 = cstart[tid], s1 = cstart[tid + 1];
        float m = -INFINITY;
        for (int p = s0; p < s1; p++) m = fmaxf(m, logit[ceid[p]]);
        float den = 0.0f;
        for (int p = s0; p < s1; p++) {
            float ex = expf(logit[ceid[p]] - m);
            den += ex;
            alpha[ceid[p]] = ex;
        }
        float inv = 1.0f / (den + 1e-16f);
        for (int p = s0; p < s1; p++) alpha[ceid[p]] *= inv;
    }
    __syncthreads();
    for (int n = 0; n < NN; n++) {
        int s0 = cstart[n], s1 = cstart[n + 1];
        float acc = 0.0f;
        for (int p = s0; p < s1; p++) {
            int e = ceid[p];
            acc = fmaf(alpha[e], hl[csrc[e] * C2 + tid], acc);
        }
        float o = acc + b;
        o = o > 0.0f ? o : expm1f(o);
        long idx = ((long)n * TT + t) * C2 + tid;
        __nv_bfloat16 hi = __float2bfloat16(o);
        d_seqh[idx] = hi;
        d_seql[idx] = __float2bfloat16(o - __bfloat162float(hi));
    }
}

// ---------- K4a: init xpre1 with biases ----------
__global__ __launch_bounds__(512) void k_xpre_init() {
    d_xpre1[blockIdx.x * Z1 + threadIdx.x] = d_lb1[threadIdx.x];
}

// ---------- K4: GEMM2 wmma NT, split-K z=4, atomic epilogue ----------
__global__ __launch_bounds__(256) void k_gemm2() {
    extern __shared__ __align__(16) __nv_bfloat16 smb[];
    __nv_bfloat16* Ah = smb;
    __nv_bfloat16* Al = Ah + 128 * 72;
    __nv_bfloat16* Bh = Al + 128 * 72;
    __nv_bfloat16* Bl = Bh + 64 * 72;
    int bx = blockIdx.x, by = blockIdx.y, bz = blockIdx.z;
    int tid = threadIdx.x, warp = tid >> 5, lane = tid & 31;
    int wm = warp >> 1, wn = warp & 1;

    wmma::fragment<wmma::accumulator, 16, 16, 16, float> acc[2][2];
#pragma unroll
    for (int i = 0; i < 2; i++)
#pragma unroll
        for (int j = 0; j < 2; j++) wmma::fill_fragment(acc[i][j], 0.0f);

    const __nv_bfloat16* Agh = d_seqh + (long)(by * 128) * NC2;
    const __nv_bfloat16* Agl = d_seql + (long)(by * 128) * NC2;
    const __nv_bfloat16* Bgh = d_wihh + (long)(bx * 64) * NC2;
    const __nv_bfloat16* Bgl = d_wihl + (long)(bx * 64) * NC2;

    int kbase = bz * (NC2 / 4);
    for (int ch = 0; ch < (NC2 / 4) / 64; ch++) {
        int k0 = kbase + ch * 64;
#pragma unroll
        for (int i = 0; i < 4; i++) {
            int idx = tid + i * 256;
            int row = idx >> 3, c8 = (idx & 7) * 8;
            *(int4*)&Ah[row * 72 + c8] = *(const int4*)&Agh[(long)row * NC2 + k0 + c8];
            *(int4*)&Al[row * 72 + c8] = *(const int4*)&Agl[(long)row * NC2 + k0 + c8];
        }
#pragma unroll
        for (int i = 0; i < 2; i++) {
            int idx = tid + i * 256;
            int nr = idx >> 3, c8 = (idx & 7) * 8;
            *(int4*)&Bh[nr * 72 + c8] = *(const int4*)&Bgh[(long)nr * NC2 + k0 + c8];
            *(int4*)&Bl[nr * 72 + c8] = *(const int4*)&Bgl[(long)nr * NC2 + k0 + c8];
        }
        __syncthreads();
#pragma unroll
        for (int k16 = 0; k16 < 4; k16++) {
            wmma::fragment<wmma::matrix_a, 16, 16, 16, __nv_bfloat16, wmma::row_major> ah[2], al[2];
#pragma unroll
            for (int i = 0; i < 2; i++) {
                wmma::load_matrix_sync(ah[i], Ah + (wm * 32 + i * 16) * 72 + k16 * 16, 72);
                wmma::load_matrix_sync(al[i], Al + (wm * 32 + i * 16) * 72 + k16 * 16, 72);
            }
            wmma::fragment<wmma::matrix_b, 16, 16, 16, __nv_bfloat16, wmma::col_major> bh[2], bl[2];
#pragma unroll
            for (int j = 0; j < 2; j++) {
                wmma::load_matrix_sync(bh[j], Bh + (wn * 32 + j * 16) * 72 + k16 * 16, 72);
                wmma::load_matrix_sync(bl[j], Bl + (wn * 32 + j * 16) * 72 + k16 * 16, 72);
            }
#pragma unroll
            for (int i = 0; i < 2; i++)
#pragma unroll
                for (int j = 0; j < 2; j++) {
                    wmma::mma_sync(acc[i][j], ah[i], bh[j], acc[i][j]);
                    wmma::mma_sync(acc[i][j], ah[i], bl[j], acc[i][j]);
                    wmma::mma_sync(acc[i][j], al[i], bh[j], acc[i][j]);
                }
        }
        __syncthreads();
    }
    float* stage = (float*)smb;
    float* ws = stage + warp * (32 * 36);
#pragma unroll
    for (int i = 0; i < 2; i++)
#pragma unroll
        for (int j = 0; j < 2; j++)
            wmma::store_matrix_sync(ws + i * 16 * 36 + j * 16, acc[i][j], 36, wmma::mem_row_major);
    __syncwarp();
    int m0 = by * 128 + wm * 32;
    int n0 = bx * 64 + wn * 32;
    for (int k = 0; k < 32; k++)
        atomicAdd(&d_xpre1[(m0 + k) * Z1 + n0 + lane], ws[k * 36 + lane]);
}

// ---------- K5: LSTM1 — replicated-group update, group barriers, fast activations ----------
__global__ __launch_bounds__(512, 1) void k_lstm1(const float* __restrict__ whh) {
    int j = threadIdx.x;
    int jj = j & 127;
    int grp = j >> 7;
    extern __shared__ float sm[];
    float* sw   = sm;                          // (WSM/4)*512*4
    float* hsm4 = sw + (WSM / 4) * 512 * 4;    // 4 copies x 128
    float* zs0  = hsm4 + 512;
    float* zs1  = zs0 + 512;

    ull wd[WREG / 2];
#pragma unroll
    for (int q4 = 0; q4 < WREG / 4; q4++) {
        ulonglong2 v = *(const ulonglong2*)(whh + j * HID1 + 4 * q4);
        wd[2 * q4] = v.x; wd[2 * q4 + 1] = v.y;
    }
#pragma unroll
    for (int kk4 = 0; kk4 < WSM / 4; kk4++)
        ((float4*)sw)[kk4 * 512 + j] = *(const float4*)(whh + j * HID1 + WREG + kk4 * 4);
    hsm4[j] = 0.0f;
    float c = 0.0f;
    __syncthreads();

    const ulonglong2* h2 = (const ulonglong2*)(hsm4 + grp * 128);
    const ulonglong2* sw2 = (const ulonglong2*)sw;
    float xv = d_xpre1[j];
    for (int t = 0; t < TT; t++) {
        ull pa = pk2(xv, 0.0f), pb = 0ull;
#pragma unroll
        for (int q4 = 0; q4 < WREG / 4; q4++) {
            ulonglong2 hv = h2[q4];
            pa = ffma2(wd[2 * q4],     hv.x, pa);
            pb = ffma2(wd[2 * q4 + 1], hv.y, pb);
        }
#pragma unroll
        for (int kk4 = 0; kk4 < WSM / 4; kk4++) {
            ulonglong2 w = sw2[kk4 * 512 + j];
            ulonglong2 hv = h2[WREG / 4 + kk4];
            pa = ffma2(w.x, hv.x, pa);
            pb = ffma2(w.y, hv.y, pb);
        }
        float2 fa = upk2(pa), fb = upk2(pb);
        float z = (fa.x + fb.x) + (fa.y + fb.y);
        float* zw = (t & 1) ? zs1 : zs0;
        zw[j] = (grp == 2) ? ftanh(z) : fsigm(z);
        if (t + 1 < TT) xv = d_xpre1[(t + 1) * Z1 + j];
        __syncthreads();
        float ai = zw[jj], af = zw[128 + jj], ag = zw[256 + jj], ao = zw[384 + jj];
        c = af * c + ai * ag;
        float h = ao * ftanh(c);
        hsm4[j] = h;
        if (grp == 0) d_hs1[t * HID1 + jj] = h;
        asm volatile("bar.sync %0, 128;" :: "r"(1 + grp) : "memory");
    }
}

// ---------- K6: xpre2 ----------
__global__ __launch_bounds__(256) void k_xpre2(const float* __restrict__ wih2) {
    int t = blockIdx.x;
    int tid = threadIdx.x;
    __shared__ __align__(16) float h[HID1];
    if (tid < HID1) h[tid] = d_hs1[t * HID1 + tid];
    __syncthreads();
    const ulonglong2* w2 = (const ulonglong2*)(wih2 + tid * HID1);
    const ulonglong2* h2 = (const ulonglong2*)h;
    ull pa = 0ull, pb = 0ull;
#pragma unroll
    for (int q4 = 0; q4 < HID1 / 4; q4++) {
        ulonglong2 w = w2[q4], hv = h2[q4];
        pa = ffma2(w.x, hv.x, pa);
        pb = ffma2(w.y, hv.y, pb);
    }
    float2 fa = upk2(pa), fb = upk2(pb);
    d_xpre2[t * Z2 + tid] = (fa.x + fb.x) + (fa.y + fb.y) + d_lb2[tid];
}

// ---------- K7: LSTM2 + FC — replicated-group update ----------
__global__ __launch_bounds__(256, 1) void k_lstm2(const float* __restrict__ whh2,
                                                  const float* __restrict__ fcw,
                                                  const float* __restrict__ fcb,
                                                  float* __restrict__ out) {
    int j = threadIdx.x;
    int jj = j & 63;
    int grp = j >> 6;
    __shared__ __align__(16) float hsm4[256];
    __shared__ float zs0[Z2];
    __shared__ float zs1[Z2];
    ull wd[HID2 / 2];
#pragma unroll
    for (int q4 = 0; q4 < HID2 / 4; q4++) {
        ulonglong2 v = *(const ulonglong2*)(whh2 + j * HID2 + 4 * q4);
        wd[2 * q4] = v.x; wd[2 * q4 + 1] = v.y;
    }
    hsm4[j] = 0.0f;
    float c = 0.0f;
    __syncthreads();
    const ulonglong2* h2 = (const ulonglong2*)(hsm4 + grp * 64);
    float xv = d_xpre2[j];
    for (int t = 0; t < TT; t++) {
        ull pa = pk2(xv, 0.0f), pb = 0ull;
#pragma unroll
        for (int q4 = 0; q4 < HID2 / 4; q4++) {
            ulonglong2 hv = h2[q4];
            pa = ffma2(wd[2 * q4],     hv.x, pa);
            pb = ffma2(wd[2 * q4 + 1], hv.y, pb);
        }
        float2 fa = upk2(pa), fb = upk2(pb);
        float z = (fa.x + fb.x) + (fa.y + fb.y);
        float* zw = (t & 1) ? zs1 : zs0;
        zw[j] = (grp == 2) ? ftanh(z) : fsigm(z);
        if (t + 1 < TT) xv = d_xpre2[(t + 1) * Z2 + j];
        __syncthreads();
        float ai = zw[jj], af = zw[64 + jj], ag = zw[128 + jj], ao = zw[192 + jj];
        c = af * c + ai * ag;
        hsm4[j] = ao * ftanh(c);
        asm volatile("bar.sync %0, 64;" :: "r"(1 + grp) : "memory");
    }
    if (j < 4) {
        float acc = fcb[j];
        for (int k = 0; k < HID2; k++) acc = fmaf(fcw[j * HID2 + k], hsm4[k], acc);
        out[j] = acc;
    }
}

extern "C" void kernel_launch(void* const* d_in, const int* in_sizes, int n_in,
                              void* d_out, int out_size) {
    const float* x      = (const float*)d_in[0];
    const int*   ei     = (const int*)d_in[1];
    const float* ea     = (const float*)d_in[2];
    const float* g1_wl  = (const float*)d_in[3];
    const float* g1_wr  = (const float*)d_in[4];
    const float* g1_we  = (const float*)d_in[5];
    const float* g1_att = (const float*)d_in[6];
    const float* g1_b   = (const float*)d_in[7];
    const float* g2_wl  = (const float*)d_in[8];
    const float* g2_wr  = (const float*)d_in[9];
    const float* g2_we  = (const float*)d_in[10];
    const float* g2_att = (const float*)d_in[11];
    const float* g2_b   = (const float*)d_in[12];
    const float* l1_wih = (const float*)d_in[13];
    const float* l1_whh = (const float*)d_in[14];
    const float* l1_bih = (const float*)d_in[15];
    const float* l1_bhh = (const float*)d_in[16];
    const float* l2_wih = (const float*)d_in[17];
    const float* l2_whh = (const float*)d_in[18];
    const float* l2_bih = (const float*)d_in[19];
    const float* l2_bhh = (const float*)d_in[20];
    const float* fc_w   = (const float*)d_in[21];
    const float* fc_b   = (const float*)d_in[22];
    float* out = (float*)d_out;

    const int SMEM_GAT1  = (16896 + 776 + 776 + 68) * 4 + 325 * 4;
    const int SMEM_GAT2  = (16896 + 104 + 104) * 4 + 325 * 4;
    const int SMEM_LSTM1 = ((WSM / 4) * 512 * 4 + 512 + 1024) * 4;
    const int SMEM_GEMM  = (128 * 72 * 2 + 64 * 72 * 2) * 2;   // 55296 bytes
    cudaFuncSetAttribute(k_gat1, cudaFuncAttributeMaxDynamicSharedMemorySize, SMEM_GAT1);
    cudaFuncSetAttribute(k_gat2, cudaFuncAttributeMaxDynamicSharedMemorySize, SMEM_GAT2);
    cudaFuncSetAttribute(k_lstm1, cudaFuncAttributeMaxDynamicSharedMemorySize, SMEM_LSTM1);
    cudaFuncSetAttribute(k_gemm1, cudaFuncAttributeMaxDynamicSharedMemorySize, SMEM_GEMM);
    cudaFuncSetAttribute(k_gemm2, cudaFuncAttributeMaxDynamicSharedMemorySize, SMEM_GEMM);

    k_setup<<<1, 512>>>(ei, ea, g1_we, g2_we, l1_bih, l1_bhh, l2_bih, l2_bhh);
    k_split_w1<<<512, 256>>>(g2_wl, g2_wr);
    k_split_w2<<<512, 256>>>(l1_wih);
    k_gat1<<<TT, 512, SMEM_GAT1>>>(x, g1_wl, g1_wr, g1_att, g1_b);
    k_gemm1<<<dim3(16, 264), 256, SMEM_GEMM>>>();
    k_gat2<<<TT, 512, SMEM_GAT2>>>(g2_att, g2_b);
    k_xpre_init<<<TT, Z1>>>();
    k_gemm2<<<dim3(8, 8, 4), 256, SMEM_GEMM>>>();
    k_lstm1<<<1, 512, SMEM_LSTM1>>>(l1_whh);
    k_xpre2<<<TT, 256>>>(l2_wih);
    k_lstm2<<<1, 256>>>(l2_whh, fc_w, fc_b, out);
}